// round 5
// baseline (speedup 1.0000x reference)
#include <cuda_runtime.h>
#include <cuda_bf16.h>

// GCN: 4 layers, N=100000 nodes, F dims 64->32->16->8->64, E=3,200,000 edges.
// out[v] = sum_{e:(s->v)} h[s]*norm[e] + h[v]*dinv[v]^2 + b ; relu between layers.
// deg[v] = (#incoming edges) + 1 (self loop); dinv = rsqrt(deg); norm = dinv[s]*dinv[d].
//
// edge_index dtype is ambiguous (reference says int64; JAX default silently
// downcasts to int32). Detected ON DEVICE per launch: int32 data read as int64
// yields values >= 2^32 with overwhelming probability.

#define N_NODES 100000
#define N_EDGES 3200000

// ---------------- scratch (static device globals; no allocation) ----------------
__device__ __align__(16) int   g_src[N_EDGES];
__device__ __align__(16) int   g_dst[N_EDGES];
__device__ __align__(16) float g_norm[N_EDGES];
__device__ __align__(16) float g_deg[N_NODES];
__device__ __align__(16) float g_dinv[N_NODES];
__device__ int                 g_is_i32;             // dtype flag
__device__ __align__(16) float g_h[N_NODES * 64];    // gather source (post-GEMM)
__device__ __align__(16) float g_accA[N_NODES * 64]; // ping
__device__ __align__(16) float g_accB[N_NODES * 64]; // pong

static inline int cdiv(long long a, int b) { return (int)((a + b - 1) / b); }

// ---------------- vectorized reduction (sm_90+: red.global.add.v4.f32) ----------
__device__ __forceinline__ void red_add_v4(float* addr, float4 v) {
    asm volatile("red.global.add.v4.f32 [%0], {%1, %2, %3, %4};"
                 :: "l"(addr), "f"(v.x), "f"(v.y), "f"(v.z), "f"(v.w)
                 : "memory");
}

// ---------------- dtype detection + preprocessing ----------------
__global__ void detect_dtype_kernel(const long long* __restrict__ ei64) {
    // One block. If ANY of the first 2048 int64-interpreted words is outside
    // [0, N_NODES), the buffer must be int32 (two packed ids per word).
    __shared__ int bad;
    if (threadIdx.x == 0) bad = 0;
    __syncthreads();
    for (int i = threadIdx.x; i < 2048; i += blockDim.x) {
        long long v = ei64[i];
        if (v < 0 || v >= N_NODES) bad = 1;   // benign race, all writes set 1
    }
    __syncthreads();
    if (threadIdx.x == 0) g_is_i32 = bad;
}

__global__ void init_deg_kernel() {
    unsigned i = blockIdx.x * blockDim.x + threadIdx.x;
    if (i < N_NODES) g_deg[i] = 1.0f;  // self loop
}

__global__ void prep_edges_kernel(const void* __restrict__ ei_raw) {
    unsigned e = blockIdx.x * blockDim.x + threadIdx.x;
    if (e >= N_EDGES) return;
    int s, d;
    if (g_is_i32) {
        const int* ei = (const int*)ei_raw;
        s = ei[e];
        d = ei[N_EDGES + e];
    } else {
        const long long* ei = (const long long*)ei_raw;
        s = (int)ei[e];
        d = (int)ei[N_EDGES + e];
    }
    // defensive clamp: no dtype confusion may ever produce a wild atomic
    s &= 0x7fffffff; if (s >= N_NODES) s %= N_NODES;
    d &= 0x7fffffff; if (d >= N_NODES) d %= N_NODES;
    g_src[e] = s;
    g_dst[e] = d;
    atomicAdd(&g_deg[d], 1.0f);  // integer-valued fp32 sums: order-independent
}

__global__ void dinv_kernel() {
    unsigned i = blockIdx.x * blockDim.x + threadIdx.x;
    if (i < N_NODES) g_dinv[i] = rsqrtf(g_deg[i]);
}

__global__ void norm_kernel() {
    unsigned e = blockIdx.x * blockDim.x + threadIdx.x;
    if (e >= N_EDGES) return;
    g_norm[e] = g_dinv[g_src[e]] * g_dinv[g_dst[e]];
}

// ---------------- fused GEMM + self-loop + bias init ----------------
// hout[n,j] = act(in[n,:]) @ W[:,j]  (act = relu if RELU)
// acc [n,j] = b[j] + hout[n,j]*dinv[n]^2   (seed accumulator for the scatter)
template <int DIN, int DOUT, bool RELU>
__global__ void gemm_kernel(const float* __restrict__ in,
                            const float* __restrict__ W,
                            const float* __restrict__ b,
                            float* __restrict__ hout,
                            float* __restrict__ acc) {
    __shared__ float Ws[DIN * DOUT];
    __shared__ float bs[DOUT];
    for (int i = threadIdx.x; i < DIN * DOUT; i += blockDim.x) Ws[i] = W[i];
    if (threadIdx.x < DOUT) bs[threadIdx.x] = b[threadIdx.x];
    __syncthreads();

    unsigned idx = blockIdx.x * blockDim.x + threadIdx.x;
    if (idx >= (unsigned)N_NODES * DOUT) return;
    unsigned node = idx / DOUT;         // DOUT pow2 -> shift
    unsigned j    = idx & (DOUT - 1);

    const float* row = in + (size_t)node * DIN;
    float s = 0.0f;
#pragma unroll
    for (int k = 0; k < DIN; k++) {
        float a = row[k];
        if (RELU) a = fmaxf(a, 0.0f);
        s = fmaf(a, Ws[k * DOUT + j], s);
    }
    hout[idx] = s;
    float di = g_dinv[node];
    acc[idx] = fmaf(s, di * di, bs[j]);
}

// ---------------- edge scatter: acc[dst] += h[src] * norm ----------------
// DOUT/4 threads per edge; each thread handles one float4 chunk.
template <int DOUT>
__global__ void scatter_kernel(const float4* __restrict__ h,
                               float* __restrict__ acc) {
    constexpr int TPE = DOUT / 4;                 // float4 chunks per edge
    unsigned gid = blockIdx.x * blockDim.x + threadIdx.x;
    if (gid >= (unsigned)N_EDGES * TPE) return;
    unsigned e = gid / TPE;                        // TPE pow2 -> shift
    unsigned j = gid & (TPE - 1);

    int   s = __ldg(&g_src[e]);
    int   d = __ldg(&g_dst[e]);
    float w = __ldg(&g_norm[e]);

    float4 v = h[(size_t)s * TPE + j];
    v.x *= w; v.y *= w; v.z *= w; v.w *= w;
    red_add_v4(acc + (size_t)d * DOUT + j * 4, v);
}

// ---------------- launch ----------------
extern "C" void kernel_launch(void* const* d_in, const int* in_sizes, int n_in,
                              void* d_out, int out_size) {
    const float* x  = (const float*)d_in[0];
    const float* W1 = (const float*)d_in[2];
    const float* b1 = (const float*)d_in[3];
    const float* W2 = (const float*)d_in[4];
    const float* b2 = (const float*)d_in[5];
    const float* W3 = (const float*)d_in[6];
    const float* b3 = (const float*)d_in[7];
    const float* W4 = (const float*)d_in[8];
    const float* b4 = (const float*)d_in[9];
    float* out = (float*)d_out;

    float *h, *accA, *accB;
    cudaGetSymbolAddress((void**)&h,    g_h);
    cudaGetSymbolAddress((void**)&accA, g_accA);
    cudaGetSymbolAddress((void**)&accB, g_accB);

    const int T = 256;

    // --- graph normalization (recomputed every call; deterministic) ---
    detect_dtype_kernel<<<1, 256>>>((const long long*)d_in[1]);
    init_deg_kernel<<<cdiv(N_NODES, T), T>>>();
    prep_edges_kernel<<<cdiv(N_EDGES, T), T>>>(d_in[1]);
    dinv_kernel<<<cdiv(N_NODES, T), T>>>();
    norm_kernel<<<cdiv(N_EDGES, T), T>>>();

    // --- layer 1: 64 -> 32 (input x, no relu) ---
    gemm_kernel<64, 32, false><<<cdiv((long long)N_NODES * 32, T), T>>>(x, W1, b1, h, accA);
    scatter_kernel<32><<<cdiv((long long)N_EDGES * 8, T), T>>>((const float4*)h, accA);

    // --- layer 2: 32 -> 16 (relu on accA) ---
    gemm_kernel<32, 16, true><<<cdiv((long long)N_NODES * 16, T), T>>>(accA, W2, b2, h, accB);
    scatter_kernel<16><<<cdiv((long long)N_EDGES * 4, T), T>>>((const float4*)h, accB);

    // --- layer 3: 16 -> 8 (relu on accB) ---
    gemm_kernel<16, 8, true><<<cdiv((long long)N_NODES * 8, T), T>>>(accB, W3, b3, h, accA);
    scatter_kernel<8><<<cdiv((long long)N_EDGES * 2, T), T>>>((const float4*)h, accA);

    // --- layer 4: 8 -> 64 (relu on accA), accumulate directly into d_out ---
    gemm_kernel<8, 64, true><<<cdiv((long long)N_NODES * 64, T), T>>>(accA, W4, b4, h, out);
    scatter_kernel<64><<<cdiv((long long)N_EDGES * 16, T), T>>>((const float4*)h, out);
}

// round 7
// speedup vs baseline: 1.3688x; 1.3688x over previous
#include <cuda_runtime.h>
#include <cuda_bf16.h>

// GCN: 4 layers, N=100000 nodes, dims 64->32->16->8->64, E=3,200,000 edges.
// out = conv4(relu(conv3(relu(conv2(relu(conv1(x)))))))
// conv(x) = Aggregate(x@W) + b,  Aggregate includes self loop with dinv^2.
//
// Layer-4 trick: aggregation is linear and relu precedes the GEMM, so
//   Aggregate(relu(z3)@W4) = Aggregate(relu(z3)) @ W4
// -> aggregate in 8-dim space (32B rows) instead of 64-dim (256B rows).
//
// edge_index dtype detected on device (JAX silently downcasts int64->int32).

#define N_NODES 100000
#define N_EDGES 3200000

// ---------------- scratch (static device globals; no allocation) ----------------
__device__ __align__(16) int2  g_edge[N_EDGES];      // (src, dst)
__device__ __align__(16) float g_norm[N_EDGES];
__device__ __align__(16) float g_deg[N_NODES];
__device__ int                 g_is_i32;
__device__ __align__(16) float g_h[N_NODES * 64];    // gather source
__device__ __align__(16) float g_accA[N_NODES * 64]; // ping
__device__ __align__(16) float g_accB[N_NODES * 64]; // pong

static inline int cdiv(long long a, int b) { return (int)((a + b - 1) / b); }

// ---------------- vectorized reduction (sm_90+: red.global.add.v4.f32) ----------
__device__ __forceinline__ void red_add_v4(float* addr, float4 v) {
    asm volatile("red.global.add.v4.f32 [%0], {%1, %2, %3, %4};"
                 :: "l"(addr), "f"(v.x), "f"(v.y), "f"(v.z), "f"(v.w)
                 : "memory");
}

// ---------------- prep: dtype detect + deg init (fused) ----------------
__global__ void init_detect_kernel(const long long* __restrict__ ei64) {
    unsigned i = blockIdx.x * blockDim.x + threadIdx.x;
    if (i < N_NODES) g_deg[i] = 1.0f;               // self loop
    if (blockIdx.x == 0) {
        // int32 data read as int64 packs two ids per word -> value >= 2^32
        // (or out of [0,N)) with overwhelming probability over 2048 words.
        __shared__ int bad;
        if (threadIdx.x == 0) bad = 0;
        __syncthreads();
        for (int k = threadIdx.x; k < 2048; k += blockDim.x) {
            long long v = ei64[k];
            if (v < 0 || v >= N_NODES) bad = 1;     // benign race
        }
        __syncthreads();
        if (threadIdx.x == 0) g_is_i32 = bad;
    }
}

__global__ void prep_edges_kernel(const void* __restrict__ ei_raw) {
    unsigned e = blockIdx.x * blockDim.x + threadIdx.x;
    if (e >= N_EDGES) return;
    int s, d;
    if (g_is_i32) {
        const int* ei = (const int*)ei_raw;
        s = ei[e]; d = ei[N_EDGES + e];
    } else {
        const long long* ei = (const long long*)ei_raw;
        s = (int)ei[e]; d = (int)ei[N_EDGES + e];
    }
    s &= 0x7fffffff; if (s >= N_NODES) s %= N_NODES;   // defensive clamp
    d &= 0x7fffffff; if (d >= N_NODES) d %= N_NODES;
    g_edge[e] = make_int2(s, d);
    atomicAdd(&g_deg[d], 1.0f);     // integer-valued fp32: order-independent
}

__global__ void norm_kernel() {
    unsigned e = blockIdx.x * blockDim.x + threadIdx.x;
    if (e >= N_EDGES) return;
    int2 sd = g_edge[e];
    g_norm[e] = rsqrtf(g_deg[sd.x]) * rsqrtf(g_deg[sd.y]);
}

// ---------------- fused GEMM (+optional relu on input, +optional seed) --------
// SEED: hout = in@W ; acc = b + hout*dinv^2   (accumulator seeded for scatter)
// !SEED (final layer): acc = in@W + b         (direct output, no hout)
template <int DIN, int DOUT, bool RELU, bool SEED>
__global__ void gemm_kernel(const float* __restrict__ in,
                            const float* __restrict__ W,
                            const float* __restrict__ b,
                            float* __restrict__ hout,
                            float* __restrict__ acc) {
    __shared__ float Ws[DIN * DOUT];
    __shared__ float bs[DOUT];
    for (int i = threadIdx.x; i < DIN * DOUT; i += blockDim.x) Ws[i] = W[i];
    if (threadIdx.x < DOUT) bs[threadIdx.x] = b[threadIdx.x];
    __syncthreads();

    unsigned idx = blockIdx.x * blockDim.x + threadIdx.x;
    if (idx >= (unsigned)N_NODES * DOUT) return;
    unsigned node = idx / DOUT;           // DOUT pow2 -> shift
    unsigned j    = idx & (DOUT - 1);

    const float* row = in + (size_t)node * DIN;
    float s = 0.0f;
#pragma unroll
    for (int k = 0; k < DIN; k++) {
        float a = row[k];
        if (RELU) a = fmaxf(a, 0.0f);
        s = fmaf(a, Ws[k * DOUT + j], s);
    }
    if (SEED) {
        hout[idx] = s;
        float di = rsqrtf(g_deg[node]);
        acc[idx] = fmaf(s, di * di, bs[j]);
    } else {
        acc[idx] = s + bs[j];
    }
}

// ---- layer-4 pre-aggregation: r3 = relu(z3); seed acc = r3 * dinv^2 ----
__global__ void relu_seed8_kernel(const float* __restrict__ z3,
                                  float* __restrict__ r3,
                                  float* __restrict__ acc) {
    unsigned idx = blockIdx.x * blockDim.x + threadIdx.x;
    if (idx >= (unsigned)N_NODES * 8) return;
    unsigned node = idx >> 3;
    float r = fmaxf(z3[idx], 0.0f);
    r3[idx] = r;
    float di = rsqrtf(g_deg[node]);
    acc[idx] = r * di * di;
}

// ---------------- edge scatter: acc[dst] += h[src] * norm ----------------
template <int DOUT>
__global__ void scatter_kernel(const float4* __restrict__ h,
                               float* __restrict__ acc) {
    constexpr int TPE = DOUT / 4;                 // float4 chunks per edge
    unsigned gid = blockIdx.x * blockDim.x + threadIdx.x;
    if (gid >= (unsigned)N_EDGES * TPE) return;
    unsigned e = gid / TPE;                        // TPE pow2 -> shift
    unsigned j = gid & (TPE - 1);

    int2  sd = __ldg(&g_edge[e]);
    float w  = __ldg(&g_norm[e]);

    float4 v = h[(size_t)sd.x * TPE + j];
    v.x *= w; v.y *= w; v.z *= w; v.w *= w;
    red_add_v4(acc + (size_t)sd.y * DOUT + j * 4, v);
}

// ---------------- launch ----------------
extern "C" void kernel_launch(void* const* d_in, const int* in_sizes, int n_in,
                              void* d_out, int out_size) {
    const float* x  = (const float*)d_in[0];
    const float* W1 = (const float*)d_in[2];
    const float* b1 = (const float*)d_in[3];
    const float* W2 = (const float*)d_in[4];
    const float* b2 = (const float*)d_in[5];
    const float* W3 = (const float*)d_in[6];
    const float* b3 = (const float*)d_in[7];
    const float* W4 = (const float*)d_in[8];
    const float* b4 = (const float*)d_in[9];
    float* out = (float*)d_out;

    float *h, *accA, *accB;
    cudaGetSymbolAddress((void**)&h,    g_h);
    cudaGetSymbolAddress((void**)&accA, g_accA);
    cudaGetSymbolAddress((void**)&accB, g_accB);

    const int T = 256;

    // --- graph normalization ---
    init_detect_kernel<<<cdiv(N_NODES, T), T>>>((const long long*)d_in[1]);
    prep_edges_kernel<<<cdiv(N_EDGES, T), T>>>(d_in[1]);
    norm_kernel<<<cdiv(N_EDGES, T), T>>>();

    // --- conv1: 64 -> 32 ---
    gemm_kernel<64, 32, false, true><<<cdiv((long long)N_NODES * 32, T), T>>>(x, W1, b1, h, accA);
    scatter_kernel<32><<<cdiv((long long)N_EDGES * 8, T), T>>>((const float4*)h, accA);

    // --- conv2: 32 -> 16 (relu on z1) ---
    gemm_kernel<32, 16, true, true><<<cdiv((long long)N_NODES * 16, T), T>>>(accA, W2, b2, h, accB);
    scatter_kernel<16><<<cdiv((long long)N_EDGES * 4, T), T>>>((const float4*)h, accB);

    // --- conv3: 16 -> 8 (relu on z2) ---
    gemm_kernel<16, 8, true, true><<<cdiv((long long)N_NODES * 8, T), T>>>(accB, W3, b3, h, accA);
    scatter_kernel<8><<<cdiv((long long)N_EDGES * 2, T), T>>>((const float4*)h, accA);

    // --- conv4: aggregate relu(z3) in 8-dim, THEN apply W4 (linearity) ---
    relu_seed8_kernel<<<cdiv((long long)N_NODES * 8, T), T>>>(accA, h, accB);
    scatter_kernel<8><<<cdiv((long long)N_EDGES * 2, T), T>>>((const float4*)h, accB);
    gemm_kernel<8, 64, false, false><<<cdiv((long long)N_NODES * 64, T), T>>>(accB, W4, b4, nullptr, out);
}

// round 9
// speedup vs baseline: 2.2650x; 1.6547x over previous
#include <cuda_runtime.h>
#include <cuda_bf16.h>

// GCN: 4 layers, N=100000 nodes, dims 64->32->16->8->64, E=3,200,000 edges.
//
// Factored normalization: norm(e) = dinv[s]*dinv[d].
//   h'[n]  = (in @ W)[n] * dinv[n]                (gemm, pre-scaled by src factor)
//   raw[d] = h'[d] + sum_{e:(s->d)} h'[s]         (pull-based CSR aggregation)
//   z[d]   = raw[d]*dinv[d] + b                   (folded into NEXT gemm's input
//                                                  transform: relu(raw*dinv + b))
// Layer 4 uses linearity: Agg(relu(z3)) @ W4 + b4, aggregated in 8-dim space.
//
// Pull-based padded CSR: edges binned by dst (CAP=128 slots/node; deg~Poisson(32),
// overflow probability ~0, guarded). Aggregation = coalesced row loads + register
// accumulation + one store per node. Zero atomics in the hot path.
//
// edge_index dtype detected on device (JAX silently downcasts int64->int32).

#define N_NODES 100000
#define N_EDGES 3200000
#define CAP     128      // max in-edges stored per node

// ---------------- scratch (static device globals; no allocation) ----------------
__device__ __align__(16) int   g_csr[(size_t)N_NODES * CAP]; // src ids, binned by dst
__device__ __align__(16) int   g_cnt[N_NODES];               // in-degree (edges only)
__device__ int                 g_is_i32;
__device__ __align__(16) float g_h[N_NODES * 64];            // h' (gather source)
__device__ __align__(16) float g_raw[N_NODES * 64];          // aggregation output

static inline int cdiv(long long a, int b) { return (int)((a + b - 1) / b); }

__device__ __forceinline__ float node_dinv(int n) {
    return rsqrtf((float)g_cnt[n] + 1.0f);   // +1 self loop
}

// ---------------- prep: cnt=0 + dtype detect ----------------
__global__ void init_detect_kernel(const long long* __restrict__ ei64) {
    unsigned i = blockIdx.x * blockDim.x + threadIdx.x;
    if (i < N_NODES) g_cnt[i] = 0;
    if (blockIdx.x == 0) {
        // int32 data read as int64 packs two ids per word -> value out of
        // [0, N_NODES) with overwhelming probability over 2048 words.
        __shared__ int bad;
        if (threadIdx.x == 0) bad = 0;
        __syncthreads();
        for (int k = threadIdx.x; k < 2048; k += blockDim.x) {
            long long v = ei64[k];
            if (v < 0 || v >= N_NODES) bad = 1;   // benign race
        }
        __syncthreads();
        if (threadIdx.x == 0) g_is_i32 = bad;
    }
}

// ---------------- prep: bin edges into padded CSR ----------------
__global__ void prep_fill_kernel(const void* __restrict__ ei_raw) {
    unsigned e = blockIdx.x * blockDim.x + threadIdx.x;
    if (e >= N_EDGES) return;
    int s, d;
    if (g_is_i32) {
        const int* ei = (const int*)ei_raw;
        s = ei[e]; d = ei[N_EDGES + e];
    } else {
        const long long* ei = (const long long*)ei_raw;
        s = (int)ei[e]; d = (int)ei[N_EDGES + e];
    }
    s &= 0x7fffffff; if (s >= N_NODES) s %= N_NODES;   // defensive clamp
    d &= 0x7fffffff; if (d >= N_NODES) d %= N_NODES;
    int slot = atomicAdd(&g_cnt[d], 1);
    if (slot < CAP) g_csr[(size_t)d * CAP + slot] = s;
}

// ---------------- GEMM: thread-per-node, h' = transform(in)@W * dinv ----------
// MODE 0: a = in[k]                         (layer 1: raw input x)
// MODE 1: a = relu(in[k]*dinv + bprev[k])   (hidden layers: fold prev z)
template <int DIN, int DOUT, int MODE>
__global__ void gemm_kernel(const float* __restrict__ in,
                            const float* __restrict__ W,
                            const float* __restrict__ bprev,
                            float* __restrict__ hout) {
    __shared__ float Ws[DIN * DOUT];
    __shared__ float bs[DIN];
    for (int i = threadIdx.x; i < DIN * DOUT; i += blockDim.x) Ws[i] = W[i];
    if (MODE == 1 && threadIdx.x < DIN) bs[threadIdx.x] = bprev[threadIdx.x];
    __syncthreads();

    int node = blockIdx.x * blockDim.x + threadIdx.x;
    if (node >= N_NODES) return;
    float dinv = node_dinv(node);

    constexpr int D4 = DOUT / 4;
    float4 s4[D4];
#pragma unroll
    for (int q = 0; q < D4; q++) s4[q] = make_float4(0.f, 0.f, 0.f, 0.f);

    const float4* row = (const float4*)(in + (size_t)node * DIN);
    const float4* W4p = (const float4*)Ws;
#pragma unroll
    for (int c = 0; c < DIN / 4; c++) {
        float4 r = row[c];
        float a[4] = {r.x, r.y, r.z, r.w};
#pragma unroll
        for (int q = 0; q < 4; q++) {
            int k = 4 * c + q;
            float av = a[q];
            if (MODE == 1) av = fmaxf(fmaf(av, dinv, bs[k]), 0.0f);
#pragma unroll
            for (int j = 0; j < D4; j++) {
                float4 w = W4p[k * D4 + j];
                s4[j].x = fmaf(av, w.x, s4[j].x);
                s4[j].y = fmaf(av, w.y, s4[j].y);
                s4[j].z = fmaf(av, w.z, s4[j].z);
                s4[j].w = fmaf(av, w.w, s4[j].w);
            }
        }
    }
    float4* outv = (float4*)(hout + (size_t)node * DOUT);
#pragma unroll
    for (int q = 0; q < D4; q++) {
        s4[q].x *= dinv; s4[q].y *= dinv; s4[q].z *= dinv; s4[q].w *= dinv;
        outv[q] = s4[q];
    }
}

// ---------------- final GEMM: out = (raw*dinv)@W4 + b4 ----------------
__global__ void gemm_final_kernel(const float* __restrict__ raw,
                                  const float* __restrict__ W,
                                  const float* __restrict__ bout,
                                  float* __restrict__ out) {
    constexpr int DIN = 8, DOUT = 64, D4 = DOUT / 4;
    __shared__ float Ws[DIN * DOUT];
    __shared__ float bs[DOUT];
    for (int i = threadIdx.x; i < DIN * DOUT; i += blockDim.x) Ws[i] = W[i];
    if (threadIdx.x < DOUT) bs[threadIdx.x] = bout[threadIdx.x];
    __syncthreads();

    int node = blockIdx.x * blockDim.x + threadIdx.x;
    if (node >= N_NODES) return;
    float dinv = node_dinv(node);

    float4 s4[D4];
    const float4* bsv = (const float4*)bs;
#pragma unroll
    for (int q = 0; q < D4; q++) s4[q] = bsv[q];

    const float4* row = (const float4*)(raw + (size_t)node * DIN);
    const float4* W4p = (const float4*)Ws;
#pragma unroll
    for (int c = 0; c < DIN / 4; c++) {
        float4 r = row[c];
        float a[4] = {r.x, r.y, r.z, r.w};
#pragma unroll
        for (int q = 0; q < 4; q++) {
            int k = 4 * c + q;
            float av = a[q] * dinv;
#pragma unroll
            for (int j = 0; j < D4; j++) {
                float4 w = W4p[k * D4 + j];
                s4[j].x = fmaf(av, w.x, s4[j].x);
                s4[j].y = fmaf(av, w.y, s4[j].y);
                s4[j].z = fmaf(av, w.z, s4[j].z);
                s4[j].w = fmaf(av, w.w, s4[j].w);
            }
        }
    }
    float4* outv = (float4*)(out + (size_t)node * DOUT);
#pragma unroll
    for (int q = 0; q < D4; q++) outv[q] = s4[q];
}

// ---- layer-4 pre-aggregation: h = relu(raw3*dinv + b3) * dinv (8-dim) ----
__global__ void seed8_kernel(const float* __restrict__ raw,
                             const float* __restrict__ b3,
                             float* __restrict__ h) {
    unsigned idx = blockIdx.x * blockDim.x + threadIdx.x;
    if (idx >= (unsigned)N_NODES * 8) return;
    int node = idx >> 3;
    int k = idx & 7;
    float dinv = node_dinv(node);
    h[idx] = fmaxf(fmaf(raw[idx], dinv, __ldg(&b3[k])), 0.0f) * dinv;
}

// ---------------- pull aggregation: raw[d] = h[d] + sum_src h[src] ----------
// DOUT lanes cooperate per destination node; per edge one coalesced row load.
template <int DOUT>
__global__ void agg_kernel(const float* __restrict__ h,
                           float* __restrict__ raw) {
    unsigned gid = blockIdx.x * blockDim.x + threadIdx.x;
    if (gid >= (unsigned)N_NODES * DOUT) return;
    int node = gid / DOUT;               // DOUT pow2 -> shift
    int j    = gid & (DOUT - 1);

    float acc = h[(size_t)node * DOUT + j];          // self loop (pre-scaled)
    int n = g_cnt[node];
    if (n > CAP) n = CAP;
    const int* lst = g_csr + (size_t)node * CAP;
    for (int i = 0; i < n; i++) {
        int s = __ldg(&lst[i]);                      // broadcast across lanes
        acc += __ldg(&h[(size_t)s * DOUT + j]);      // coalesced row load
    }
    raw[(size_t)node * DOUT + j] = acc;
}

// ---------------- launch ----------------
extern "C" void kernel_launch(void* const* d_in, const int* in_sizes, int n_in,
                              void* d_out, int out_size) {
    const float* x  = (const float*)d_in[0];
    const float* W1 = (const float*)d_in[2];
    const float* b1 = (const float*)d_in[3];
    const float* W2 = (const float*)d_in[4];
    const float* b2 = (const float*)d_in[5];
    const float* W3 = (const float*)d_in[6];
    const float* b3 = (const float*)d_in[7];
    const float* W4 = (const float*)d_in[8];
    const float* b4 = (const float*)d_in[9];
    float* out = (float*)d_out;

    float *h, *raw;
    cudaGetSymbolAddress((void**)&h,   g_h);
    cudaGetSymbolAddress((void**)&raw, g_raw);

    const int T = 256;

    // --- prep: degree count + padded-CSR binning ---
    init_detect_kernel<<<cdiv(N_NODES, T), T>>>((const long long*)d_in[1]);
    prep_fill_kernel<<<cdiv(N_EDGES, T), T>>>(d_in[1]);

    // --- conv1: 64 -> 32 ---
    gemm_kernel<64, 32, 0><<<cdiv(N_NODES, 128), 128>>>(x, W1, nullptr, h);
    agg_kernel<32><<<cdiv((long long)N_NODES * 32, T), T>>>(h, raw);

    // --- conv2: 32 -> 16 (z1 = raw*dinv + b1, relu folded) ---
    gemm_kernel<32, 16, 1><<<cdiv(N_NODES, 128), 128>>>(raw, W2, b1, h);
    agg_kernel<16><<<cdiv((long long)N_NODES * 16, T), T>>>(h, raw);

    // --- conv3: 16 -> 8 (z2 folded) ---
    gemm_kernel<16, 8, 1><<<cdiv(N_NODES, 128), 128>>>(raw, W3, b2, h);
    agg_kernel<8><<<cdiv((long long)N_NODES * 8, T), T>>>(h, raw);

    // --- conv4: aggregate relu(z3) in 8-dim, then apply W4 (linearity) ---
    seed8_kernel<<<cdiv((long long)N_NODES * 8, T), T>>>(raw, b3, h);
    agg_kernel<8><<<cdiv((long long)N_NODES * 8, T), T>>>(h, raw);
    gemm_final_kernel<<<cdiv(N_NODES, 128), 128>>>(raw, W4, b4, out);
}

// round 10
// speedup vs baseline: 2.6601x; 1.1744x over previous
#include <cuda_runtime.h>
#include <cuda_bf16.h>

// GCN: 4 layers, N=100000 nodes, dims 64->32->16->8->64, E=3,200,000 edges.
//
// Factored normalization: norm(e) = dinv[s]*dinv[d].
//   h'[n]  = (in @ W)[n] * dinv[n]         (gemm, pre-scaled by src factor)
//   raw[d] = h'[d] + sum_{e:(s->d)} h'[s]  (pull-based CSR aggregation)
//   z[d]   = raw[d]*dinv[d] + b            (folded into next gemm's input)
// Layer 4 via linearity: Agg(relu(z3)) @ W4 + b4, aggregated in 8-dim space.
//
// Aggregation is float4-vectorized (DOUT/4 lanes per node) with int4 index
// loads and 4x unroll: minimizes LDG instruction count (LSU-issue was the
// measured bottleneck: alu 40%, issue 58%, DRAM 7%).
//
// edge_index dtype detected on device (JAX silently downcasts int64->int32).

#define N_NODES 100000
#define N_EDGES 3200000
#define CAP     128      // max in-edges stored per node (deg~Poisson(32))

// ---------------- scratch (static device globals; no allocation) ----------------
__device__ __align__(16) int   g_csr[(size_t)N_NODES * CAP]; // src ids, binned by dst
__device__ __align__(16) int   g_cnt[N_NODES];               // in-degree (edges only)
__device__ int                 g_is_i32;
__device__ __align__(16) float g_h[N_NODES * 64];            // h' (gather source)
__device__ __align__(16) float g_raw[N_NODES * 64];          // aggregation output

static inline int cdiv(long long a, int b) { return (int)((a + b - 1) / b); }

__device__ __forceinline__ float node_dinv(int n) {
    return rsqrtf((float)g_cnt[n] + 1.0f);   // +1 self loop
}

// ---------------- prep: cnt=0 + dtype detect ----------------
__global__ void init_detect_kernel(const long long* __restrict__ ei64) {
    unsigned i = blockIdx.x * blockDim.x + threadIdx.x;
    if (i < N_NODES) g_cnt[i] = 0;
    if (blockIdx.x == 0) {
        __shared__ int bad;
        if (threadIdx.x == 0) bad = 0;
        __syncthreads();
        for (int k = threadIdx.x; k < 2048; k += blockDim.x) {
            long long v = ei64[k];
            if (v < 0 || v >= N_NODES) bad = 1;   // benign race
        }
        __syncthreads();
        if (threadIdx.x == 0) g_is_i32 = bad;
    }
}

// ---------------- prep: bin edges into padded CSR ----------------
__global__ void prep_fill_kernel(const void* __restrict__ ei_raw) {
    unsigned e = blockIdx.x * blockDim.x + threadIdx.x;
    if (e >= N_EDGES) return;
    int s, d;
    if (g_is_i32) {
        const int* ei = (const int*)ei_raw;
        s = ei[e]; d = ei[N_EDGES + e];
    } else {
        const long long* ei = (const long long*)ei_raw;
        s = (int)ei[e]; d = (int)ei[N_EDGES + e];
    }
    s &= 0x7fffffff; if (s >= N_NODES) s %= N_NODES;   // defensive clamp
    d &= 0x7fffffff; if (d >= N_NODES) d %= N_NODES;
    int slot = atomicAdd(&g_cnt[d], 1);
    if (slot < CAP) g_csr[(size_t)d * CAP + slot] = s;
}

// ---------------- GEMM: thread-per-node, h' = transform(in)@W * dinv ----------
// MODE 0: a = in[k]                         (layer 1: raw input x)
// MODE 1: a = relu(in[k]*dinv + bprev[k])   (hidden layers: fold prev z)
template <int DIN, int DOUT, int MODE>
__global__ void gemm_kernel(const float* __restrict__ in,
                            const float* __restrict__ W,
                            const float* __restrict__ bprev,
                            float* __restrict__ hout) {
    __shared__ float Ws[DIN * DOUT];
    __shared__ float bs[DIN];
    for (int i = threadIdx.x; i < DIN * DOUT; i += blockDim.x) Ws[i] = W[i];
    if (MODE == 1 && threadIdx.x < DIN) bs[threadIdx.x] = bprev[threadIdx.x];
    __syncthreads();

    int node = blockIdx.x * blockDim.x + threadIdx.x;
    if (node >= N_NODES) return;
    float dinv = node_dinv(node);

    constexpr int D4 = DOUT / 4;
    float4 s4[D4];
#pragma unroll
    for (int q = 0; q < D4; q++) s4[q] = make_float4(0.f, 0.f, 0.f, 0.f);

    const float4* row = (const float4*)(in + (size_t)node * DIN);
    const float4* W4p = (const float4*)Ws;
#pragma unroll
    for (int c = 0; c < DIN / 4; c++) {
        float4 r = row[c];
        float a[4] = {r.x, r.y, r.z, r.w};
#pragma unroll
        for (int q = 0; q < 4; q++) {
            int k = 4 * c + q;
            float av = a[q];
            if (MODE == 1) av = fmaxf(fmaf(av, dinv, bs[k]), 0.0f);
#pragma unroll
            for (int j = 0; j < D4; j++) {
                float4 w = W4p[k * D4 + j];
                s4[j].x = fmaf(av, w.x, s4[j].x);
                s4[j].y = fmaf(av, w.y, s4[j].y);
                s4[j].z = fmaf(av, w.z, s4[j].z);
                s4[j].w = fmaf(av, w.w, s4[j].w);
            }
        }
    }
    float4* outv = (float4*)(hout + (size_t)node * DOUT);
#pragma unroll
    for (int q = 0; q < D4; q++) {
        s4[q].x *= dinv; s4[q].y *= dinv; s4[q].z *= dinv; s4[q].w *= dinv;
        outv[q] = s4[q];
    }
}

// ---------------- final GEMM: out = (raw*dinv)@W4 + b4 ----------------
__global__ void gemm_final_kernel(const float* __restrict__ raw,
                                  const float* __restrict__ W,
                                  const float* __restrict__ bout,
                                  float* __restrict__ out) {
    constexpr int DIN = 8, DOUT = 64, D4 = DOUT / 4;
    __shared__ float Ws[DIN * DOUT];
    __shared__ float bs[DOUT];
    for (int i = threadIdx.x; i < DIN * DOUT; i += blockDim.x) Ws[i] = W[i];
    if (threadIdx.x < DOUT) bs[threadIdx.x] = bout[threadIdx.x];
    __syncthreads();

    int node = blockIdx.x * blockDim.x + threadIdx.x;
    if (node >= N_NODES) return;
    float dinv = node_dinv(node);

    float4 s4[D4];
    const float4* bsv = (const float4*)bs;
#pragma unroll
    for (int q = 0; q < D4; q++) s4[q] = bsv[q];

    const float4* row = (const float4*)(raw + (size_t)node * DIN);
    const float4* W4p = (const float4*)Ws;
#pragma unroll
    for (int c = 0; c < DIN / 4; c++) {
        float4 r = row[c];
        float a[4] = {r.x, r.y, r.z, r.w};
#pragma unroll
        for (int q = 0; q < 4; q++) {
            int k = 4 * c + q;
            float av = a[q] * dinv;
#pragma unroll
            for (int j = 0; j < D4; j++) {
                float4 w = W4p[k * D4 + j];
                s4[j].x = fmaf(av, w.x, s4[j].x);
                s4[j].y = fmaf(av, w.y, s4[j].y);
                s4[j].z = fmaf(av, w.z, s4[j].z);
                s4[j].w = fmaf(av, w.w, s4[j].w);
            }
        }
    }
    float4* outv = (float4*)(out + (size_t)node * DOUT);
#pragma unroll
    for (int q = 0; q < D4; q++) outv[q] = s4[q];
}

// ---- layer-4 pre-aggregation: h = relu(raw3*dinv + b3) * dinv (8-dim, f4) ----
__global__ void seed8_kernel(const float4* __restrict__ raw,
                             const float* __restrict__ b3,
                             float4* __restrict__ h) {
    unsigned idx = blockIdx.x * blockDim.x + threadIdx.x;   // (node, half)
    if (idx >= (unsigned)N_NODES * 2) return;
    int node = idx >> 1;
    int half = idx & 1;
    float dinv = node_dinv(node);
    float4 r = raw[idx];
    float4 bv = *(const float4*)(b3 + half * 4);
    float4 o;
    o.x = fmaxf(fmaf(r.x, dinv, bv.x), 0.0f) * dinv;
    o.y = fmaxf(fmaf(r.y, dinv, bv.y), 0.0f) * dinv;
    o.z = fmaxf(fmaf(r.z, dinv, bv.z), 0.0f) * dinv;
    o.w = fmaxf(fmaf(r.w, dinv, bv.w), 0.0f) * dinv;
    h[idx] = o;
}

// ---------------- pull aggregation (float4 lanes): raw[d] = h[d] + sum h[src] --
// DOUT/4 lanes per node; per edge each lane loads one float4 (LDG.128).
// Index list read as int4 (4 edges per LDG); 4x unroll for MLP.
template <int DOUT>
__global__ void agg_kernel(const float4* __restrict__ h,
                           float4* __restrict__ raw) {
    constexpr int TPE = DOUT / 4;                  // float4 lanes per node
    unsigned gid = blockIdx.x * blockDim.x + threadIdx.x;
    if (gid >= (unsigned)N_NODES * TPE) return;
    int node = gid / TPE;                          // TPE pow2 -> shift
    int j    = gid & (TPE - 1);

    float4 acc = h[(size_t)node * TPE + j];        // self loop (pre-scaled)
    int n = g_cnt[node];
    if (n > CAP) n = CAP;
    const int* lst = g_csr + (size_t)node * CAP;   // 16B-aligned (CAP%4==0)

    int i = 0;
    for (; i + 4 <= n; i += 4) {
        int4 s4 = *(const int4*)(lst + i);         // 4 src ids, one LDG.128
        float4 v0 = h[(size_t)s4.x * TPE + j];
        float4 v1 = h[(size_t)s4.y * TPE + j];
        float4 v2 = h[(size_t)s4.z * TPE + j];
        float4 v3 = h[(size_t)s4.w * TPE + j];
        acc.x += (v0.x + v1.x) + (v2.x + v3.x);
        acc.y += (v0.y + v1.y) + (v2.y + v3.y);
        acc.z += (v0.z + v1.z) + (v2.z + v3.z);
        acc.w += (v0.w + v1.w) + (v2.w + v3.w);
    }
    for (; i < n; i++) {
        int s = __ldg(&lst[i]);
        float4 v = h[(size_t)s * TPE + j];
        acc.x += v.x; acc.y += v.y; acc.z += v.z; acc.w += v.w;
    }
    raw[(size_t)node * TPE + j] = acc;
}

// ---------------- launch ----------------
extern "C" void kernel_launch(void* const* d_in, const int* in_sizes, int n_in,
                              void* d_out, int out_size) {
    const float* x  = (const float*)d_in[0];
    const float* W1 = (const float*)d_in[2];
    const float* b1 = (const float*)d_in[3];
    const float* W2 = (const float*)d_in[4];
    const float* b2 = (const float*)d_in[5];
    const float* W3 = (const float*)d_in[6];
    const float* b3 = (const float*)d_in[7];
    const float* W4 = (const float*)d_in[8];
    const float* b4 = (const float*)d_in[9];
    float* out = (float*)d_out;

    float *h, *raw;
    cudaGetSymbolAddress((void**)&h,   g_h);
    cudaGetSymbolAddress((void**)&raw, g_raw);
    float4* h4   = (float4*)h;
    float4* raw4 = (float4*)raw;

    const int T = 256;

    // --- prep: degree count + padded-CSR binning ---
    init_detect_kernel<<<cdiv(N_NODES, T), T>>>((const long long*)d_in[1]);
    prep_fill_kernel<<<cdiv(N_EDGES, T), T>>>(d_in[1]);

    // --- conv1: 64 -> 32 ---
    gemm_kernel<64, 32, 0><<<cdiv(N_NODES, 128), 128>>>(x, W1, nullptr, h);
    agg_kernel<32><<<cdiv((long long)N_NODES * 8, T), T>>>(h4, raw4);

    // --- conv2: 32 -> 16 (z1 = raw*dinv + b1, relu folded) ---
    gemm_kernel<32, 16, 1><<<cdiv(N_NODES, 128), 128>>>(raw, W2, b1, h);
    agg_kernel<16><<<cdiv((long long)N_NODES * 4, T), T>>>(h4, raw4);

    // --- conv3: 16 -> 8 (z2 folded) ---
    gemm_kernel<16, 8, 1><<<cdiv(N_NODES, 128), 128>>>(raw, W3, b2, h);
    agg_kernel<8><<<cdiv((long long)N_NODES * 2, T), T>>>(h4, raw4);

    // --- conv4: aggregate relu(z3) in 8-dim, then apply W4 (linearity) ---
    seed8_kernel<<<cdiv((long long)N_NODES * 2, T), T>>>(raw4, b3, h4);
    agg_kernel<8><<<cdiv((long long)N_NODES * 2, T), T>>>(h4, raw4);
    gemm_final_kernel<<<cdiv(N_NODES, 128), 128>>>(raw, W4, b4, out);
}

// round 11
// speedup vs baseline: 2.6818x; 1.0081x over previous
#include <cuda_runtime.h>
#include <cuda_bf16.h>

// GCN: 4 layers, N=100000 nodes, dims 64->32->16->8->64, E=3,200,000 edges.
//
// Factored normalization: norm(e) = dinv[s]*dinv[d].
//   h'[n]  = (in @ W)[n] * dinv[n]         (gemm, pre-scaled by src factor)
//   raw[d] = h'[d] + sum_{e:(s->d)} h'[s]  (pull-based CSR aggregation)
//   z[d]   = raw[d]*dinv[d] + b            (folded into next gemm's input)
// Layer 4 via linearity: Agg(relu(z3)) @ W4 + b4, aggregated in 8-dim space.
// conv3's agg applies the relu/scale transform in its epilogue (EPI), feeding
// conv4's aggregation directly (seed kernel eliminated).
//
// Aggregation: float4 lanes (DOUT/4 per node), int4 index loads, 8x unroll
// (MLP=8 vs measured L2-latency-bound smaller aggs). agg32 is at the LTS cap.
//
// edge_index dtype detected on device (JAX silently downcasts int64->int32).

#define N_NODES 100000
#define N_EDGES 3200000
#define CAP     128      // max in-edges stored per node (deg~Poisson(32))

// ---------------- scratch (static device globals; no allocation) ----------------
__device__ __align__(16) int   g_csr[(size_t)N_NODES * CAP]; // src ids, binned by dst
__device__ __align__(16) int   g_cnt[N_NODES];               // in-degree (edges only)
__device__ int                 g_is_i32;
__device__ __align__(16) float g_h[N_NODES * 64];            // buffer A
__device__ __align__(16) float g_raw[N_NODES * 64];          // buffer B

static inline int cdiv(long long a, int b) { return (int)((a + b - 1) / b); }

__device__ __forceinline__ float node_dinv(int n) {
    return rsqrtf((float)g_cnt[n] + 1.0f);   // +1 self loop
}

// ---------------- prep: cnt=0 + dtype detect ----------------
__global__ void init_detect_kernel(const long long* __restrict__ ei64) {
    unsigned i = blockIdx.x * blockDim.x + threadIdx.x;
    if (i < N_NODES) g_cnt[i] = 0;
    if (blockIdx.x == 0) {
        __shared__ int bad;
        if (threadIdx.x == 0) bad = 0;
        __syncthreads();
        for (int k = threadIdx.x; k < 2048; k += blockDim.x) {
            long long v = ei64[k];
            if (v < 0 || v >= N_NODES) bad = 1;   // benign race
        }
        __syncthreads();
        if (threadIdx.x == 0) g_is_i32 = bad;
    }
}

// ---------------- prep: bin edges into padded CSR ----------------
__global__ void prep_fill_kernel(const void* __restrict__ ei_raw) {
    unsigned e = blockIdx.x * blockDim.x + threadIdx.x;
    if (e >= N_EDGES) return;
    int s, d;
    if (g_is_i32) {
        const int* ei = (const int*)ei_raw;
        s = ei[e]; d = ei[N_EDGES + e];
    } else {
        const long long* ei = (const long long*)ei_raw;
        s = (int)ei[e]; d = (int)ei[N_EDGES + e];
    }
    s &= 0x7fffffff; if (s >= N_NODES) s %= N_NODES;   // defensive clamp
    d &= 0x7fffffff; if (d >= N_NODES) d %= N_NODES;
    int slot = atomicAdd(&g_cnt[d], 1);
    if (slot < CAP) g_csr[(size_t)d * CAP + slot] = s;
}

// ---------------- GEMM: thread-per-node, h' = transform(in)@W * dinv ----------
// MODE 0: a = in[k]                         (layer 1: raw input x)
// MODE 1: a = relu(in[k]*dinv + bprev[k])   (hidden layers: fold prev z)
template <int DIN, int DOUT, int MODE>
__global__ void gemm_kernel(const float* __restrict__ in,
                            const float* __restrict__ W,
                            const float* __restrict__ bprev,
                            float* __restrict__ hout) {
    __shared__ float Ws[DIN * DOUT];
    __shared__ float bs[DIN];
    for (int i = threadIdx.x; i < DIN * DOUT; i += blockDim.x) Ws[i] = W[i];
    if (MODE == 1 && threadIdx.x < DIN) bs[threadIdx.x] = bprev[threadIdx.x];
    __syncthreads();

    int node = blockIdx.x * blockDim.x + threadIdx.x;
    if (node >= N_NODES) return;
    float dinv = node_dinv(node);

    constexpr int D4 = DOUT / 4;
    float4 s4[D4];
#pragma unroll
    for (int q = 0; q < D4; q++) s4[q] = make_float4(0.f, 0.f, 0.f, 0.f);

    const float4* row = (const float4*)(in + (size_t)node * DIN);
    const float4* W4p = (const float4*)Ws;
#pragma unroll
    for (int c = 0; c < DIN / 4; c++) {
        float4 r = row[c];
        float a[4] = {r.x, r.y, r.z, r.w};
#pragma unroll
        for (int q = 0; q < 4; q++) {
            int k = 4 * c + q;
            float av = a[q];
            if (MODE == 1) av = fmaxf(fmaf(av, dinv, bs[k]), 0.0f);
#pragma unroll
            for (int j = 0; j < D4; j++) {
                float4 w = W4p[k * D4 + j];
                s4[j].x = fmaf(av, w.x, s4[j].x);
                s4[j].y = fmaf(av, w.y, s4[j].y);
                s4[j].z = fmaf(av, w.z, s4[j].z);
                s4[j].w = fmaf(av, w.w, s4[j].w);
            }
        }
    }
    float4* outv = (float4*)(hout + (size_t)node * DOUT);
#pragma unroll
    for (int q = 0; q < D4; q++) {
        s4[q].x *= dinv; s4[q].y *= dinv; s4[q].z *= dinv; s4[q].w *= dinv;
        outv[q] = s4[q];
    }
}

// ---------------- final GEMM: out = (raw*dinv)@W4 + b4 ----------------
__global__ void gemm_final_kernel(const float* __restrict__ raw,
                                  const float* __restrict__ W,
                                  const float* __restrict__ bout,
                                  float* __restrict__ out) {
    constexpr int DIN = 8, DOUT = 64, D4 = DOUT / 4;
    __shared__ float Ws[DIN * DOUT];
    __shared__ float bs[DOUT];
    for (int i = threadIdx.x; i < DIN * DOUT; i += blockDim.x) Ws[i] = W[i];
    if (threadIdx.x < DOUT) bs[threadIdx.x] = bout[threadIdx.x];
    __syncthreads();

    int node = blockIdx.x * blockDim.x + threadIdx.x;
    if (node >= N_NODES) return;
    float dinv = node_dinv(node);

    float4 s4[D4];
    const float4* bsv = (const float4*)bs;
#pragma unroll
    for (int q = 0; q < D4; q++) s4[q] = bsv[q];

    const float4* row = (const float4*)(raw + (size_t)node * DIN);
    const float4* W4p = (const float4*)Ws;
#pragma unroll
    for (int c = 0; c < DIN / 4; c++) {
        float4 r = row[c];
        float a[4] = {r.x, r.y, r.z, r.w};
#pragma unroll
        for (int q = 0; q < 4; q++) {
            int k = 4 * c + q;
            float av = a[q] * dinv;
#pragma unroll
            for (int j = 0; j < D4; j++) {
                float4 w = W4p[k * D4 + j];
                s4[j].x = fmaf(av, w.x, s4[j].x);
                s4[j].y = fmaf(av, w.y, s4[j].y);
                s4[j].z = fmaf(av, w.z, s4[j].z);
                s4[j].w = fmaf(av, w.w, s4[j].w);
            }
        }
    }
    float4* outv = (float4*)(out + (size_t)node * DOUT);
#pragma unroll
    for (int q = 0; q < D4; q++) outv[q] = s4[q];
}

// ---------------- pull aggregation (float4 lanes, unroll 8) ----------------
// acc[d] = h[d] + sum_{src} h[src].  EPI: write relu(acc*dinv + b)*dinv
// (conv3 -> conv4 handoff, replaces the separate seed kernel).
template <int DOUT, bool EPI>
__global__ void agg_kernel(const float4* __restrict__ h,
                           float4* __restrict__ raw,
                           const float* __restrict__ bvec) {
    constexpr int TPE = DOUT / 4;                  // float4 lanes per node
    unsigned gid = blockIdx.x * blockDim.x + threadIdx.x;
    if (gid >= (unsigned)N_NODES * TPE) return;
    int node = gid / TPE;                          // TPE pow2 -> shift
    int j    = gid & (TPE - 1);

    float4 acc = h[(size_t)node * TPE + j];        // self loop (pre-scaled)
    int n = g_cnt[node];
    if (n > CAP) n = CAP;
    const int* lst = g_csr + (size_t)node * CAP;   // 16B-aligned (CAP%4==0)

    int i = 0;
    for (; i + 8 <= n; i += 8) {                   // MLP=8
        int4 a4 = *(const int4*)(lst + i);
        int4 b4 = *(const int4*)(lst + i + 4);
        float4 v0 = h[(size_t)a4.x * TPE + j];
        float4 v1 = h[(size_t)a4.y * TPE + j];
        float4 v2 = h[(size_t)a4.z * TPE + j];
        float4 v3 = h[(size_t)a4.w * TPE + j];
        float4 v4 = h[(size_t)b4.x * TPE + j];
        float4 v5 = h[(size_t)b4.y * TPE + j];
        float4 v6 = h[(size_t)b4.z * TPE + j];
        float4 v7 = h[(size_t)b4.w * TPE + j];
        acc.x += ((v0.x + v1.x) + (v2.x + v3.x)) + ((v4.x + v5.x) + (v6.x + v7.x));
        acc.y += ((v0.y + v1.y) + (v2.y + v3.y)) + ((v4.y + v5.y) + (v6.y + v7.y));
        acc.z += ((v0.z + v1.z) + (v2.z + v3.z)) + ((v4.z + v5.z) + (v6.z + v7.z));
        acc.w += ((v0.w + v1.w) + (v2.w + v3.w)) + ((v4.w + v5.w) + (v6.w + v7.w));
    }
    for (; i + 4 <= n; i += 4) {
        int4 a4 = *(const int4*)(lst + i);
        float4 v0 = h[(size_t)a4.x * TPE + j];
        float4 v1 = h[(size_t)a4.y * TPE + j];
        float4 v2 = h[(size_t)a4.z * TPE + j];
        float4 v3 = h[(size_t)a4.w * TPE + j];
        acc.x += (v0.x + v1.x) + (v2.x + v3.x);
        acc.y += (v0.y + v1.y) + (v2.y + v3.y);
        acc.z += (v0.z + v1.z) + (v2.z + v3.z);
        acc.w += (v0.w + v1.w) + (v2.w + v3.w);
    }
    for (; i < n; i++) {
        int s = __ldg(&lst[i]);
        float4 v = h[(size_t)s * TPE + j];
        acc.x += v.x; acc.y += v.y; acc.z += v.z; acc.w += v.w;
    }

    if (EPI) {
        float dinv = node_dinv(node);
        float4 bv = *(const float4*)(bvec + j * 4);
        acc.x = fmaxf(fmaf(acc.x, dinv, bv.x), 0.0f) * dinv;
        acc.y = fmaxf(fmaf(acc.y, dinv, bv.y), 0.0f) * dinv;
        acc.z = fmaxf(fmaf(acc.z, dinv, bv.z), 0.0f) * dinv;
        acc.w = fmaxf(fmaf(acc.w, dinv, bv.w), 0.0f) * dinv;
    }
    raw[(size_t)node * TPE + j] = acc;
}

// ---------------- launch ----------------
extern "C" void kernel_launch(void* const* d_in, const int* in_sizes, int n_in,
                              void* d_out, int out_size) {
    const float* x  = (const float*)d_in[0];
    const float* W1 = (const float*)d_in[2];
    const float* b1 = (const float*)d_in[3];
    const float* W2 = (const float*)d_in[4];
    const float* b2 = (const float*)d_in[5];
    const float* W3 = (const float*)d_in[6];
    const float* b3 = (const float*)d_in[7];
    const float* W4 = (const float*)d_in[8];
    const float* b4 = (const float*)d_in[9];
    float* out = (float*)d_out;

    float *A, *B;
    cudaGetSymbolAddress((void**)&A, g_h);
    cudaGetSymbolAddress((void**)&B, g_raw);
    float4* A4 = (float4*)A;
    float4* B4 = (float4*)B;

    const int T = 256;

    // --- prep: degree count + padded-CSR binning ---
    init_detect_kernel<<<cdiv(N_NODES, T), T>>>((const long long*)d_in[1]);
    prep_fill_kernel<<<cdiv(N_EDGES, T), T>>>(d_in[1]);

    // --- conv1: 64 -> 32 :  A = x@W1 * dinv ; B = Agg(A) ---
    gemm_kernel<64, 32, 0><<<cdiv(N_NODES, 128), 128>>>(x, W1, nullptr, A);
    agg_kernel<32, false><<<cdiv((long long)N_NODES * 8, T), T>>>(A4, B4, nullptr);

    // --- conv2: 32 -> 16 :  A = relu(B*dinv+b1)@W2 * dinv ; B = Agg(A) ---
    gemm_kernel<32, 16, 1><<<cdiv(N_NODES, 128), 128>>>(B, W2, b1, A);
    agg_kernel<16, false><<<cdiv((long long)N_NODES * 4, T), T>>>(A4, B4, nullptr);

    // --- conv3: 16 -> 8 :  A = relu(B*dinv+b2)@W3 * dinv ;
    //     B = relu(Agg(A)*dinv+b3)*dinv   (EPI: conv4 gather source) ---
    gemm_kernel<16, 8, 1><<<cdiv(N_NODES, 128), 128>>>(B, W3, b2, A);
    agg_kernel<8, true><<<cdiv((long long)N_NODES * 2, T), T>>>(A4, B4, b3);

    // --- conv4: aggregate (8-dim), then out = (A*dinv... already scaled)@W4+b4 --
    agg_kernel<8, false><<<cdiv((long long)N_NODES * 2, T), T>>>(B4, A4, nullptr);
    gemm_final_kernel<<<cdiv(N_NODES, 128), 128>>>(A, W4, b4, out);
}

// round 12
// speedup vs baseline: 2.7664x; 1.0316x over previous
#include <cuda_runtime.h>
#include <cuda_bf16.h>

// GCN: 4 layers, N=100000, dims 64->32->16->8->64, E=3,200,000.
// conv(y) = D^-1/2 Â D^-1/2 (y@W) + b,  Â = A + I.
// Factored: h' = (y@W)·dinv ; raw = Â h' ; z = raw·dinv + b.
// Layer 4 via linearity: out = (Â(relu(z3)·dinv))·dinv @ W4 + b4.
//
// Node-local GEMMs are fused into the aggregation epilogues via warp shuffles
// (a node's row lives in TPE consecutive lanes). 7 kernels total.
// agg32 measured at ~90% of LTS cap — aggregation traffic is the floor.
//
// edge_index dtype detected on device (JAX silently downcasts int64->int32).

#define N_NODES 100000
#define N_EDGES 3200000
#define CAP     128      // max in-edges per node (deg~Poisson(32))

// ---------------- scratch (static device globals; no allocation) ----------------
__device__ __align__(16) int   g_csr[(size_t)N_NODES * CAP];
__device__ __align__(16) int   g_cnt[N_NODES];
__device__ int                 g_is_i32;
__device__ __align__(16) float g_bufA[N_NODES * 32];
__device__ __align__(16) float g_bufB[N_NODES * 32];

static inline int cdiv(long long a, int b) { return (int)((a + b - 1) / b); }

__device__ __forceinline__ float node_dinv(int n) {
    return rsqrtf((float)g_cnt[n] + 1.0f);   // +1 self loop
}

// ---------------- prep: cnt=0 + dtype detect ----------------
__global__ void init_detect_kernel(const long long* __restrict__ ei64) {
    unsigned i = blockIdx.x * blockDim.x + threadIdx.x;
    if (i < N_NODES) g_cnt[i] = 0;
    if (blockIdx.x == 0) {
        __shared__ int bad;
        if (threadIdx.x == 0) bad = 0;
        __syncthreads();
        for (int k = threadIdx.x; k < 2048; k += blockDim.x) {
            long long v = ei64[k];
            if (v < 0 || v >= N_NODES) bad = 1;   // benign race
        }
        __syncthreads();
        if (threadIdx.x == 0) g_is_i32 = bad;
    }
}

// ---------------- prep: bin edges into padded CSR (4 edges/thread) ----------
__global__ void prep_fill_kernel(const void* __restrict__ ei_raw) {
    unsigned t = blockIdx.x * blockDim.x + threadIdx.x;
    unsigned e0 = t * 4;
    if (e0 >= N_EDGES) return;
    int s[4], d[4];
    if (g_is_i32) {
        const int* ei = (const int*)ei_raw;
        int4 sv = *(const int4*)(ei + e0);
        int4 dv = *(const int4*)(ei + N_EDGES + e0);
        s[0]=sv.x; s[1]=sv.y; s[2]=sv.z; s[3]=sv.w;
        d[0]=dv.x; d[1]=dv.y; d[2]=dv.z; d[3]=dv.w;
    } else {
        const long long* ei = (const long long*)ei_raw;
#pragma unroll
        for (int q = 0; q < 4; q++) {
            s[q] = (int)ei[e0 + q];
            d[q] = (int)ei[N_EDGES + e0 + q];
        }
    }
#pragma unroll
    for (int q = 0; q < 4; q++) {
        int ss = s[q] & 0x7fffffff; if (ss >= N_NODES) ss %= N_NODES;
        int dd = d[q] & 0x7fffffff; if (dd >= N_NODES) dd %= N_NODES;
        int slot = atomicAdd(&g_cnt[dd], 1);
        if (slot < CAP) g_csr[(size_t)dd * CAP + slot] = ss;
    }
}

// ---------------- gemm1: h1' = (x@W1)·dinv  (64 -> 32, thread-per-node) -------
__global__ void gemm1_kernel(const float* __restrict__ in,
                             const float* __restrict__ W,
                             float* __restrict__ hout) {
    __shared__ float Ws[64 * 32];
    for (int i = threadIdx.x; i < 64 * 32; i += blockDim.x) Ws[i] = W[i];
    __syncthreads();

    int node = blockIdx.x * blockDim.x + threadIdx.x;
    if (node >= N_NODES) return;
    float dinv = node_dinv(node);

    float4 s4[8];
#pragma unroll
    for (int q = 0; q < 8; q++) s4[q] = make_float4(0.f, 0.f, 0.f, 0.f);

    const float4* row = (const float4*)(in + (size_t)node * 64);
    const float4* W4p = (const float4*)Ws;
#pragma unroll
    for (int c = 0; c < 16; c++) {
        float4 r = row[c];
        float a[4] = {r.x, r.y, r.z, r.w};
#pragma unroll
        for (int q = 0; q < 4; q++) {
            int k = 4 * c + q;
            float av = a[q];
#pragma unroll
            for (int j = 0; j < 8; j++) {
                float4 w = W4p[k * 8 + j];
                s4[j].x = fmaf(av, w.x, s4[j].x);
                s4[j].y = fmaf(av, w.y, s4[j].y);
                s4[j].z = fmaf(av, w.z, s4[j].z);
                s4[j].w = fmaf(av, w.w, s4[j].w);
            }
        }
    }
    float4* outv = (float4*)(hout + (size_t)node * 32);
#pragma unroll
    for (int q = 0; q < 8; q++) {
        s4[q].x *= dinv; s4[q].y *= dinv; s4[q].z *= dinv; s4[q].w *= dinv;
        outv[q] = s4[q];
    }
}

// ---------------- shared agg core: raw = h[node] + sum h[src] ----------------
template <int TPE>
__device__ __forceinline__ float4 agg_pull(const float4* __restrict__ h,
                                           int node, int j) {
    float4 acc = h[(size_t)node * TPE + j];        // self loop
    int n = g_cnt[node];
    if (n > CAP) n = CAP;
    const int* lst = g_csr + (size_t)node * CAP;   // 16B aligned
    int i = 0;
    for (; i + 4 <= n; i += 4) {
        int4 a4 = *(const int4*)(lst + i);
        float4 v0 = h[(size_t)a4.x * TPE + j];
        float4 v1 = h[(size_t)a4.y * TPE + j];
        float4 v2 = h[(size_t)a4.z * TPE + j];
        float4 v3 = h[(size_t)a4.w * TPE + j];
        acc.x += (v0.x + v1.x) + (v2.x + v3.x);
        acc.y += (v0.y + v1.y) + (v2.y + v3.y);
        acc.z += (v0.z + v1.z) + (v2.z + v3.z);
        acc.w += (v0.w + v1.w) + (v2.w + v3.w);
    }
    for (; i < n; i++) {
        int s = __ldg(&lst[i]);
        float4 v = h[(size_t)s * TPE + j];
        acc.x += v.x; acc.y += v.y; acc.z += v.z; acc.w += v.w;
    }
    return acc;
}

template <int W>
__device__ __forceinline__ float4 shfl4(float4 v, int g) {
    float4 r;
    r.x = __shfl_sync(0xffffffffu, v.x, g, W);
    r.y = __shfl_sync(0xffffffffu, v.y, g, W);
    r.z = __shfl_sync(0xffffffffu, v.z, g, W);
    r.w = __shfl_sync(0xffffffffu, v.w, g, W);
    return r;
}

// ---- agg32 + gemm2: h2' = relu(Agg(h1')·dinv + b1)@W2 · dinv  (-> 16-dim) ----
__global__ void agg_gemm2_kernel(const float4* __restrict__ h,
                                 float* __restrict__ h2,
                                 const float* __restrict__ b1,
                                 const float* __restrict__ W2) {
    __shared__ float Ws[32 * 16];
    __shared__ float bs[32];
    for (int i = threadIdx.x; i < 32 * 16; i += blockDim.x) Ws[i] = W2[i];
    if (threadIdx.x < 32) bs[threadIdx.x] = b1[threadIdx.x];
    __syncthreads();

    unsigned gid = blockIdx.x * blockDim.x + threadIdx.x;
    if (gid >= (unsigned)N_NODES * 8) return;      // 800000 % 32 == 0: warp-uniform
    int node = gid >> 3;
    int j    = gid & 7;

    float4 acc = agg_pull<8>(h, node, j);
    float dinv = node_dinv(node);
    float4 z;
    z.x = fmaxf(fmaf(acc.x, dinv, bs[4 * j + 0]), 0.f);
    z.y = fmaxf(fmaf(acc.y, dinv, bs[4 * j + 1]), 0.f);
    z.z = fmaxf(fmaf(acc.z, dinv, bs[4 * j + 2]), 0.f);
    z.w = fmaxf(fmaf(acc.w, dinv, bs[4 * j + 3]), 0.f);

    float o0 = 0.f, o1 = 0.f;
    int c0 = 2 * j, c1 = 2 * j + 1;
#pragma unroll
    for (int g = 0; g < 8; g++) {
        float4 zb = shfl4<8>(z, g);
        int k = 4 * g;
        o0 = fmaf(zb.x, Ws[(k + 0) * 16 + c0], o0);
        o1 = fmaf(zb.x, Ws[(k + 0) * 16 + c1], o1);
        o0 = fmaf(zb.y, Ws[(k + 1) * 16 + c0], o0);
        o1 = fmaf(zb.y, Ws[(k + 1) * 16 + c1], o1);
        o0 = fmaf(zb.z, Ws[(k + 2) * 16 + c0], o0);
        o1 = fmaf(zb.z, Ws[(k + 2) * 16 + c1], o1);
        o0 = fmaf(zb.w, Ws[(k + 3) * 16 + c0], o0);
        o1 = fmaf(zb.w, Ws[(k + 3) * 16 + c1], o1);
    }
    *(float2*)(h2 + (size_t)node * 16 + c0) = make_float2(o0 * dinv, o1 * dinv);
}

// ---- agg16 + gemm3: h3' = relu(Agg(h2')·dinv + b2)@W3 · dinv  (-> 8-dim) ----
__global__ void agg_gemm3_kernel(const float4* __restrict__ h,
                                 float* __restrict__ h3,
                                 const float* __restrict__ b2,
                                 const float* __restrict__ W3) {
    __shared__ float Ws[16 * 8];
    __shared__ float bs[16];
    for (int i = threadIdx.x; i < 16 * 8; i += blockDim.x) Ws[i] = W3[i];
    if (threadIdx.x < 16) bs[threadIdx.x] = b2[threadIdx.x];
    __syncthreads();

    unsigned gid = blockIdx.x * blockDim.x + threadIdx.x;
    if (gid >= (unsigned)N_NODES * 4) return;      // 400000 % 32 == 0
    int node = gid >> 2;
    int j    = gid & 3;

    float4 acc = agg_pull<4>(h, node, j);
    float dinv = node_dinv(node);
    float4 z;
    z.x = fmaxf(fmaf(acc.x, dinv, bs[4 * j + 0]), 0.f);
    z.y = fmaxf(fmaf(acc.y, dinv, bs[4 * j + 1]), 0.f);
    z.z = fmaxf(fmaf(acc.z, dinv, bs[4 * j + 2]), 0.f);
    z.w = fmaxf(fmaf(acc.w, dinv, bs[4 * j + 3]), 0.f);

    float o0 = 0.f, o1 = 0.f;
    int c0 = 2 * j, c1 = 2 * j + 1;
#pragma unroll
    for (int g = 0; g < 4; g++) {
        float4 zb = shfl4<4>(z, g);
        int k = 4 * g;
        o0 = fmaf(zb.x, Ws[(k + 0) * 8 + c0], o0);
        o1 = fmaf(zb.x, Ws[(k + 0) * 8 + c1], o1);
        o0 = fmaf(zb.y, Ws[(k + 1) * 8 + c0], o0);
        o1 = fmaf(zb.y, Ws[(k + 1) * 8 + c1], o1);
        o0 = fmaf(zb.z, Ws[(k + 2) * 8 + c0], o0);
        o1 = fmaf(zb.z, Ws[(k + 2) * 8 + c1], o1);
        o0 = fmaf(zb.w, Ws[(k + 3) * 8 + c0], o0);
        o1 = fmaf(zb.w, Ws[(k + 3) * 8 + c1], o1);
    }
    *(float2*)(h3 + (size_t)node * 8 + c0) = make_float2(o0 * dinv, o1 * dinv);
}

// ---- agg8 + seed: h4' = relu(Agg(h3')·dinv + b3) · dinv  (-> 8-dim) ----
__global__ void agg_seed_kernel(const float4* __restrict__ h,
                                float4* __restrict__ h4,
                                const float* __restrict__ b3) {
    unsigned gid = blockIdx.x * blockDim.x + threadIdx.x;
    if (gid >= (unsigned)N_NODES * 2) return;      // 200000 % 32 == 0
    int node = gid >> 1;
    int j    = gid & 1;

    float4 acc = agg_pull<2>(h, node, j);
    float dinv = node_dinv(node);
    float4 bv = *(const float4*)(b3 + 4 * j);
    float4 o;
    o.x = fmaxf(fmaf(acc.x, dinv, bv.x), 0.f) * dinv;
    o.y = fmaxf(fmaf(acc.y, dinv, bv.y), 0.f) * dinv;
    o.z = fmaxf(fmaf(acc.z, dinv, bv.z), 0.f) * dinv;
    o.w = fmaxf(fmaf(acc.w, dinv, bv.w), 0.f) * dinv;
    h4[gid] = o;
}

// ---- agg8 + gemm4: out = (Agg(h4')·dinv)@W4 + b4  (-> 64-dim, d_out) ----
__global__ void agg_final_kernel(const float4* __restrict__ h,
                                 float* __restrict__ out,
                                 const float* __restrict__ W4,
                                 const float* __restrict__ b4) {
    __shared__ float Ws[8 * 64];
    __shared__ float bs[64];
    for (int i = threadIdx.x; i < 8 * 64; i += blockDim.x) Ws[i] = W4[i];
    if (threadIdx.x < 64) bs[threadIdx.x] = b4[threadIdx.x];
    __syncthreads();

    unsigned gid = blockIdx.x * blockDim.x + threadIdx.x;
    if (gid >= (unsigned)N_NODES * 2) return;      // warp-uniform
    int node = gid >> 1;
    int j    = gid & 1;

    float4 acc = agg_pull<2>(h, node, j);
    float dinv = node_dinv(node);
    float4 z;                                       // own K chunk, scaled
    z.x = acc.x * dinv; z.y = acc.y * dinv; z.z = acc.z * dinv; z.w = acc.w * dinv;

    float4 z0 = shfl4<2>(z, 0);                     // k = 0..3
    float4 z1 = shfl4<2>(z, 1);                     // k = 4..7
    float zf[8] = {z0.x, z0.y, z0.z, z0.w, z1.x, z1.y, z1.z, z1.w};

    // lane j computes output columns [32j, 32j+32)
    int cbase = 32 * j;
    float4 s4[8];
    const float4* bsv = (const float4*)(bs + cbase);
#pragma unroll
    for (int q = 0; q < 8; q++) s4[q] = bsv[q];

#pragma unroll
    for (int k = 0; k < 8; k++) {
        float av = zf[k];
        const float4* wrow = (const float4*)(Ws + k * 64 + cbase);
#pragma unroll
        for (int q = 0; q < 8; q++) {
            float4 w = wrow[q];
            s4[q].x = fmaf(av, w.x, s4[q].x);
            s4[q].y = fmaf(av, w.y, s4[q].y);
            s4[q].z = fmaf(av, w.z, s4[q].z);
            s4[q].w = fmaf(av, w.w, s4[q].w);
        }
    }
    float4* outv = (float4*)(out + (size_t)node * 64 + cbase);
#pragma unroll
    for (int q = 0; q < 8; q++) outv[q] = s4[q];
}

// ---------------- launch ----------------
extern "C" void kernel_launch(void* const* d_in, const int* in_sizes, int n_in,
                              void* d_out, int out_size) {
    const float* x  = (const float*)d_in[0];
    const float* W1 = (const float*)d_in[2];
    const float* b1 = (const float*)d_in[3];
    const float* W2 = (const float*)d_in[4];
    const float* b2 = (const float*)d_in[5];
    const float* W3 = (const float*)d_in[6];
    const float* b3 = (const float*)d_in[7];
    const float* W4 = (const float*)d_in[8];
    const float* b4 = (const float*)d_in[9];
    float* out = (float*)d_out;

    float *A, *B;
    cudaGetSymbolAddress((void**)&A, g_bufA);
    cudaGetSymbolAddress((void**)&B, g_bufB);
    float4* A4 = (float4*)A;
    float4* B4 = (float4*)B;

    const int T = 256;

    // prep
    init_detect_kernel<<<cdiv(N_NODES, T), T>>>((const long long*)d_in[1]);
    prep_fill_kernel<<<cdiv(N_EDGES / 4, T), T>>>(d_in[1]);

    // conv1 gemm: A = (x@W1)·dinv   (32-dim)
    gemm1_kernel<<<cdiv(N_NODES, 128), 128>>>(x, W1, A);
    // conv1 agg + conv2 gemm: B = h2'  (16-dim)
    agg_gemm2_kernel<<<cdiv((long long)N_NODES * 8, T), T>>>(A4, B, b1, W2);
    // conv2 agg + conv3 gemm: A = h3'  (8-dim)
    agg_gemm3_kernel<<<cdiv((long long)N_NODES * 4, T), T>>>(B4, A, b2, W3);
    // conv3 agg + relu seed:  B = h4'  (8-dim)
    agg_seed_kernel<<<cdiv((long long)N_NODES * 2, T), T>>>(A4, B4, b3);
    // conv4 agg + final gemm: out      (64-dim)
    agg_final_kernel<<<cdiv((long long)N_NODES * 2, T), T>>>(B4, out, W4, b4);
}